// round 6
// baseline (speedup 1.0000x reference)
#include <cuda_runtime.h>
#include <cstdint>
#include <math.h>

#define FILTER_LEN 1024
#define HOP        512
#define CUTOFF     513
#define BATCH      8
#define TLEN       1048576
#define NFRAMES    2049
#define XP_LEN     (TLEN + FILTER_LEN)     // 1049600

#define MROWS   1024                       // interleaved rows: f 0..511 (R,I pairs)
#define BM      128
#define BN      64
#define KC      128                        // s8 k per chunk (128 B rows)
#define NK      (FILTER_LEN / KC)          // 8

// stage: A(128 rows x 128B) limb1+limb2 + B(64 rows x 128B) limb1+limb2
#define SA1     0
#define SA2     16384
#define SB1     32768
#define SB2     40960
#define STAGE   49152                      // 48 KB
#define DSMEM   (2 * STAGE)                // 96 KB -> 2 CTAs/SM

#define NREM    (BATCH * (NFRAMES + 512))  // 20488 remainder outputs

// combine constants: x*b = (8/127^2) * (a1b1 + (a1b2 + a2b1)/128 + [dropped])
#define C1f     (8.0f / 16129.0f)
#define C2f     (C1f / 128.0f)

// ---------------- device scratch (s8 limbs) ---------------------------------
__device__ __align__(128) int8_t g_x1[(size_t)BATCH * XP_LEN];
__device__ __align__(128) int8_t g_x2[(size_t)BATCH * XP_LEN];
__device__ __align__(128) int8_t g_b1[(size_t)MROWS * FILTER_LEN];
__device__ __align__(128) int8_t g_b2[(size_t)MROWS * FILTER_LEN];

// ---------------- helpers ---------------------------------------------------
__device__ __forceinline__ uint32_t smem_u32(const void* p) {
    uint32_t a;
    asm("{ .reg .u64 t; cvta.to.shared.u64 t, %1; cvt.u32.u64 %0, t; }"
        : "=r"(a) : "l"(p));
    return a;
}
__device__ __forceinline__ void cp_async16(uint32_t dst, const void* src) {
    asm volatile("cp.async.cg.shared.global [%0], [%1], 16;"
                 :: "r"(dst), "l"(src) : "memory");
}
__device__ __forceinline__ void cp_commit() {
    asm volatile("cp.async.commit_group;" ::: "memory");
}
template <int N> __device__ __forceinline__ void cp_wait() {
    asm volatile("cp.async.wait_group %0;" :: "n"(N) : "memory");
}
__device__ __forceinline__ void ldsm_x4(uint32_t& r0, uint32_t& r1,
                                        uint32_t& r2, uint32_t& r3, uint32_t addr) {
    asm volatile("ldmatrix.sync.aligned.m8n8.x4.shared.b16 {%0,%1,%2,%3}, [%4];"
                 : "=r"(r0), "=r"(r1), "=r"(r2), "=r"(r3) : "r"(addr));
}
__device__ __forceinline__ void mma_s8(int* d, const uint32_t* a,
                                       uint32_t b0, uint32_t b1) {
    asm volatile(
        "mma.sync.aligned.m16n8k32.row.col.s32.s8.s8.s32 "
        "{%0,%1,%2,%3}, {%4,%5,%6,%7}, {%8,%9}, {%0,%1,%2,%3};"
        : "+r"(d[0]), "+r"(d[1]), "+r"(d[2]), "+r"(d[3])
        : "r"(a[0]), "r"(a[1]), "r"(a[2]), "r"(a[3]), "r"(b0), "r"(b1));
}
__device__ __forceinline__ void quant2(float v, float scale, int& q1, int& q2) {
    float t = v * scale;
    q1 = __float2int_rn(t);
    q2 = __float2int_rn((t - (float)q1) * 128.0f);
}
__device__ __forceinline__ uint32_t pack4(int a, int b, int c, int d) {
    return (uint32_t)(a & 0xFF) | ((uint32_t)(b & 0xFF) << 8)
         | ((uint32_t)(c & 0xFF) << 16) | ((uint32_t)(d & 0xFF) << 24);
}

// ---------------- prep: reflect pad + s8 two-limb quant ---------------------
__global__ void pad_quant_kernel(const float* __restrict__ x) {
    size_t v = (size_t)blockIdx.x * blockDim.x + threadIdx.x;   // 16-elem group
    if (v >= (size_t)BATCH * XP_LEN / 16) return;
    const size_t i0 = v * 16;
    const int b  = (int)(i0 / XP_LEN);
    const int p0 = (int)(i0 % XP_LEN);
    const float* xb = x + (size_t)b * TLEN;
    uint32_t w1[4], w2[4];
    #pragma unroll
    for (int g4 = 0; g4 < 4; ++g4) {
        int q1[4], q2[4];
        #pragma unroll
        for (int e = 0; e < 4; ++e) {
            int j = p0 + g4 * 4 + e - HOP;
            if (j < 0) j = -j;
            else if (j >= TLEN) j = 2 * TLEN - 2 - j;
            quant2(xb[j], 127.0f / 8.0f, q1[e], q2[e]);
        }
        w1[g4] = pack4(q1[0], q1[1], q1[2], q1[3]);
        w2[g4] = pack4(q2[0], q2[1], q2[2], q2[3]);
    }
    *reinterpret_cast<uint4*>(g_x1 + i0) = make_uint4(w1[0], w1[1], w1[2], w1[3]);
    *reinterpret_cast<uint4*>(g_x2 + i0) = make_uint4(w2[0], w2[1], w2[2], w2[3]);
}

// interleave basis rows (2f=real, 2f+1=imag) + s8 two-limb quant
__global__ void basis_quant_kernel(const float* __restrict__ basis) {
    size_t v = (size_t)blockIdx.x * blockDim.x + threadIdx.x;   // 16-elem group
    if (v >= (size_t)MROWS * FILTER_LEN / 16) return;
    const size_t i0 = v * 16;
    const int g = (int)(i0 >> 10);
    const int k = (int)(i0 & 1023);
    const int f = g >> 1;
    const int src = (g & 1) ? (f + CUTOFF) : f;
    const float* bs = basis + (size_t)src * FILTER_LEN + k;
    uint32_t w1[4], w2[4];
    #pragma unroll
    for (int g4 = 0; g4 < 4; ++g4) {
        const float4 fv = *reinterpret_cast<const float4*>(bs + g4 * 4);
        const float e4[4] = { fv.x, fv.y, fv.z, fv.w };
        int q1[4], q2[4];
        #pragma unroll
        for (int e = 0; e < 4; ++e) quant2(e4[e], 127.0f, q1[e], q2[e]);
        w1[g4] = pack4(q1[0], q1[1], q1[2], q1[3]);
        w2[g4] = pack4(q2[0], q2[1], q2[2], q2[3]);
    }
    *reinterpret_cast<uint4*>(g_b1 + i0) = make_uint4(w1[0], w1[1], w1[2], w1[3]);
    *reinterpret_cast<uint4*>(g_b2 + i0) = make_uint4(w2[0], w2[1], w2[2], w2[3]);
}

// ---------------- main: IMMA GEMM (y<8) + fp32 remainder (y==8) ------------
__global__ __launch_bounds__(256, 2)
void stft_mma_kernel(const float* __restrict__ x,
                     const float* __restrict__ basis,
                     const float* __restrict__ eps_p,
                     float* __restrict__ out)
{
    const int tid  = threadIdx.x;
    const int wid  = tid >> 5;
    const int lane = tid & 31;

    // ======== remainder: f=512 row + n=2048 column, exact fp32 =============
    if (blockIdx.y == 8) {
        const float eps = *eps_p;
        const int stride = (int)(gridDim.x * gridDim.z) * 8;
        const int wbase = (int)(blockIdx.z * gridDim.x + blockIdx.x) * 8 + wid;
        for (int o = wbase; o < NREM; o += stride) {
            const int b = o / (NFRAMES + 512);
            const int r = o % (NFRAMES + 512);
            int f, n;
            if (r < NFRAMES) { f = 512; n = r; }
            else             { f = r - NFRAMES; n = 2048; }
            const float* bR = basis + (size_t)f * FILTER_LEN;
            const float* bI = basis + (size_t)(f + CUTOFF) * FILTER_LEN;
            const float* xb = x + (size_t)b * TLEN;
            float aR = 0.f, aI = 0.f;
            #pragma unroll 4
            for (int k = lane; k < FILTER_LEN; k += 32) {
                int j = n * HOP + k - HOP;
                if (j < 0) j = -j;
                else if (j >= TLEN) j = 2 * TLEN - 2 - j;
                const float xv = xb[j];
                aR = fmaf(bR[k], xv, aR);
                aI = fmaf(bI[k], xv, aI);
            }
            #pragma unroll
            for (int s = 16; s; s >>= 1) {
                aR += __shfl_xor_sync(0xffffffffu, aR, s);
                aI += __shfl_xor_sync(0xffffffffu, aI, s);
            }
            if (lane == 0)
                out[((size_t)b * CUTOFF + f) * NFRAMES + n] =
                    sqrtf(fmaf(aR, aR, fmaf(aI, aI, eps)));
        }
        return;
    }

    // ======== dense s8 GEMM: 128m x 64n tiles ===============================
    extern __shared__ char dsm[];
    const uint32_t sbase = smem_u32(dsm);

    const int b  = blockIdx.z;
    const int m0 = blockIdx.y * BM;
    const int n0 = blockIdx.x * BN;

    const int warp_m = (wid >> 1) * 32;    // 0,32,64,96
    const int warp_n = (wid & 1) * 32;     // 0,32

    // loader geometry: A = 1024 16B chunks (4 rounds), B = 512 (2 rounds)
    int a_row[4], a_c16[4]; uint32_t a_soff[4];
    #pragma unroll
    for (int j = 0; j < 4; ++j) {
        int chunk = tid + j * 256;
        a_row[j] = chunk >> 3;
        a_c16[j] = chunk & 7;
        a_soff[j] = (uint32_t)a_row[j] * 128 + (uint32_t)((a_c16[j] ^ (a_row[j] & 7)) * 16);
    }
    int b_row[2], b_c16[2]; uint32_t b_soff[2];
    #pragma unroll
    for (int j = 0; j < 2; ++j) {
        int chunk = tid + j * 256;
        b_row[j] = chunk >> 3;
        b_c16[j] = chunk & 7;
        b_soff[j] = (uint32_t)b_row[j] * 128 + (uint32_t)((b_c16[j] ^ (b_row[j] & 7)) * 16);
    }

    const int8_t* bp1 = g_b1 + (size_t)m0 * FILTER_LEN;
    const int8_t* bp2 = g_b2 + (size_t)m0 * FILTER_LEN;
    const int8_t* xp1 = g_x1 + (size_t)b * XP_LEN + (size_t)n0 * HOP;
    const int8_t* xp2 = g_x2 + (size_t)b * XP_LEN + (size_t)n0 * HOP;

    int acc11[2][4][4], accX[2][4][4];
    #pragma unroll
    for (int mt = 0; mt < 2; ++mt)
        #pragma unroll
        for (int nt = 0; nt < 4; ++nt)
            #pragma unroll
            for (int r = 0; r < 4; ++r) { acc11[mt][nt][r] = 0; accX[mt][nt][r] = 0; }

    const int lm_r = lane & 15;
    const int lm_s = lane >> 4;

    auto load_stage = [&](int i) {
        const uint32_t st = sbase + (uint32_t)(i & 1) * STAGE;
        const int k0 = i * KC;
        #pragma unroll
        for (int j = 0; j < 4; ++j) {
            const size_t aoff = (size_t)a_row[j] * FILTER_LEN + k0 + a_c16[j] * 16;
            cp_async16(st + SA1 + a_soff[j], bp1 + aoff);
            cp_async16(st + SA2 + a_soff[j], bp2 + aoff);
        }
        #pragma unroll
        for (int j = 0; j < 2; ++j) {
            const size_t boff = (size_t)b_row[j] * HOP + k0 + b_c16[j] * 16;
            cp_async16(st + SB1 + b_soff[j], xp1 + boff);
            cp_async16(st + SB2 + b_soff[j], xp2 + boff);
        }
        cp_commit();
    };

    load_stage(0);

    for (int i = 0; i < NK; ++i) {
        if (i + 1 < NK) { load_stage(i + 1); cp_wait<1>(); }
        else            { cp_wait<0>(); }
        __syncthreads();

        const uint32_t st = sbase + (uint32_t)(i & 1) * STAGE;

        #pragma unroll
        for (int ks = 0; ks < 4; ++ks) {           // k32 step within 128B row
            const int c16 = ks * 2 + lm_s;
            uint32_t a1f[2][4], a2f[2][4];
            #pragma unroll
            for (int mt = 0; mt < 2; ++mt) {
                const int row = warp_m + mt * 16 + lm_r;
                const uint32_t ad = st + (uint32_t)row * 128
                                  + (uint32_t)((c16 ^ (row & 7)) * 16);
                ldsm_x4(a1f[mt][0], a1f[mt][1], a1f[mt][2], a1f[mt][3], ad + SA1);
                ldsm_x4(a2f[mt][0], a2f[mt][1], a2f[mt][2], a2f[mt][3], ad + SA2);
            }
            #pragma unroll
            for (int g = 0; g < 2; ++g) {
                const int row = warp_n + g * 16 + lm_r;
                const uint32_t bd = st + (uint32_t)row * 128
                                  + (uint32_t)((c16 ^ (row & 7)) * 16);
                uint32_t b1f[4], b2f[4];
                ldsm_x4(b1f[0], b1f[1], b1f[2], b1f[3], bd + SB1);
                ldsm_x4(b2f[0], b2f[1], b2f[2], b2f[3], bd + SB2);
                #pragma unroll
                for (int sub = 0; sub < 2; ++sub) {
                    const int nt = g * 2 + sub;
                    const uint32_t p10 = sub ? b1f[1] : b1f[0];
                    const uint32_t p11 = sub ? b1f[3] : b1f[2];
                    const uint32_t p20 = sub ? b2f[1] : b2f[0];
                    const uint32_t p21 = sub ? b2f[3] : b2f[2];
                    #pragma unroll
                    for (int mt = 0; mt < 2; ++mt) {
                        mma_s8(acc11[mt][nt], a1f[mt], p10, p11);   // a1*b1
                        mma_s8(accX [mt][nt], a1f[mt], p20, p21);   // a1*b2
                        mma_s8(accX [mt][nt], a2f[mt], p10, p11);   // a2*b1
                    }
                }
            }
        }
        __syncthreads();
    }

    // ---- epilogue: combine limbs, pair R/I via shfl_xor(4), magnitude -----
    const float eps = *eps_p;
    const int r4 = lane >> 2;
    const int c2 = (lane & 3) * 2;
    const bool real_holder = ((r4 & 1) == 0);

    #pragma unroll
    for (int mt = 0; mt < 2; ++mt) {
        const int mbase = m0 + warp_m + mt * 16;
        #pragma unroll
        for (int nt = 0; nt < 4; ++nt) {
            float vf[4];
            #pragma unroll
            for (int r = 0; r < 4; ++r)
                vf[r] = fmaf(C2f, (float)accX[mt][nt][r],
                             C1f * (float)acc11[mt][nt][r]);
            float p[4];
            #pragma unroll
            for (int r = 0; r < 4; ++r)
                p[r] = __shfl_xor_sync(0xffffffffu, vf[r], 4);
            if (real_holder) {
                const int nb = n0 + warp_n + nt * 8 + c2;
                const int f0r = (mbase + r4) >> 1;
                const int f1r = (mbase + r4 + 8) >> 1;
                #pragma unroll
                for (int cc = 0; cc < 2; ++cc) {
                    const int n = nb + cc;
                    float re0 = vf[cc],     im0 = p[cc];
                    float re1 = vf[2 + cc], im1 = p[2 + cc];
                    out[((size_t)b * CUTOFF + f0r) * NFRAMES + n] =
                        sqrtf(fmaf(re0, re0, fmaf(im0, im0, eps)));
                    out[((size_t)b * CUTOFF + f1r) * NFRAMES + n] =
                        sqrtf(fmaf(re1, re1, fmaf(im1, im1, eps)));
                }
            }
        }
    }
}

// ---------------- launch ----------------------------------------------------
extern "C" void kernel_launch(void* const* d_in, const int* in_sizes, int n_in,
                              void* d_out, int out_size)
{
    const float* x     = (const float*)d_in[0];
    const float* basis = (const float*)d_in[1];
    const float* eps   = (const float*)d_in[2];
    float* out = (float*)d_out;

    {
        size_t tot = (size_t)BATCH * XP_LEN / 16;
        pad_quant_kernel<<<(unsigned)((tot + 255) / 256), 256>>>(x);
    }
    {
        size_t tot = (size_t)MROWS * FILTER_LEN / 16;
        basis_quant_kernel<<<(unsigned)((tot + 255) / 256), 256>>>(basis);
    }
    {
        cudaFuncSetAttribute(stft_mma_kernel,
                             cudaFuncAttributeMaxDynamicSharedMemorySize, DSMEM);
        dim3 grid(32, 9, BATCH);     // y<8: dense GEMM; y==8: fp32 remainder
        stft_mma_kernel<<<grid, 256, DSMEM>>>(x, basis, eps, out);
    }
}

// round 7
// speedup vs baseline: 4.4533x; 4.4533x over previous
#include <cuda_runtime.h>
#include <cuda_fp16.h>
#include <cstdint>
#include <math.h>

#define FILTER_LEN 1024
#define HOP        512
#define CUTOFF     513
#define BATCH      8
#define TLEN       1048576
#define NFRAMES    2049
#define XP_LEN     (TLEN + FILTER_LEN)     // 1049600

#define MROWS   1024                       // interleaved rows: f 0..511 (R,I pairs)
#define BM      128
#define BN      128
#define KC      64                         // fp16 k per chunk (128 B rows)
#define NK      (FILTER_LEN / KC)          // 16

// stage: A(128 rows x 128B) + B(128 rows x 128B); 3 stages
#define SA      0
#define SB      16384
#define STAGE   32768
#define NSTAGE  3
#define DSMEM   (NSTAGE * STAGE)           // 96 KB -> 2 CTAs/SM

#define NREM    (BATCH * (NFRAMES + 512))  // 20488 remainder outputs

// ---------------- device scratch -------------------------------------------
__device__ __align__(128) __half g_xh[(size_t)BATCH * XP_LEN];
__device__ __align__(128) __half g_bh[(size_t)MROWS * FILTER_LEN];

// ---------------- helpers ---------------------------------------------------
__device__ __forceinline__ uint32_t smem_u32(const void* p) {
    uint32_t a;
    asm("{ .reg .u64 t; cvta.to.shared.u64 t, %1; cvt.u32.u64 %0, t; }"
        : "=r"(a) : "l"(p));
    return a;
}
__device__ __forceinline__ void cp_async16(uint32_t dst, const void* src) {
    asm volatile("cp.async.cg.shared.global [%0], [%1], 16;"
                 :: "r"(dst), "l"(src) : "memory");
}
__device__ __forceinline__ void cp_commit() {
    asm volatile("cp.async.commit_group;" ::: "memory");
}
template <int N> __device__ __forceinline__ void cp_wait() {
    asm volatile("cp.async.wait_group %0;" :: "n"(N) : "memory");
}
__device__ __forceinline__ void ldsm_x4(uint32_t& r0, uint32_t& r1,
                                        uint32_t& r2, uint32_t& r3, uint32_t addr) {
    asm volatile("ldmatrix.sync.aligned.m8n8.x4.shared.b16 {%0,%1,%2,%3}, [%4];"
                 : "=r"(r0), "=r"(r1), "=r"(r2), "=r"(r3) : "r"(addr));
}
__device__ __forceinline__ void mma_f16(float* d, const uint32_t* a,
                                        uint32_t b0, uint32_t b1) {
    asm volatile(
        "mma.sync.aligned.m16n8k16.row.col.f32.f16.f16.f32 "
        "{%0,%1,%2,%3}, {%4,%5,%6,%7}, {%8,%9}, {%0,%1,%2,%3};"
        : "+f"(d[0]), "+f"(d[1]), "+f"(d[2]), "+f"(d[3])
        : "r"(a[0]), "r"(a[1]), "r"(a[2]), "r"(a[3]), "r"(b0), "r"(b1));
}
__device__ __forceinline__ uint32_t packh2(float a, float b) {
    __half2 t = __floats2half2_rn(a, b);
    return *reinterpret_cast<uint32_t*>(&t);
}

// ---------------- prep: reflect pad -> fp16 ---------------------------------
__global__ void pad_half_kernel(const float* __restrict__ x) {
    size_t v = (size_t)blockIdx.x * blockDim.x + threadIdx.x;   // 8-elem group
    if (v >= (size_t)BATCH * XP_LEN / 8) return;
    const size_t i0 = v * 8;
    const int b  = (int)(i0 / XP_LEN);
    const int p0 = (int)(i0 % XP_LEN);
    const float* xb = x + (size_t)b * TLEN;
    float e[8];
    #pragma unroll
    for (int q = 0; q < 8; ++q) {
        int j = p0 + q - HOP;
        if (j < 0) j = -j;
        else if (j >= TLEN) j = 2 * TLEN - 2 - j;
        e[q] = xb[j];
    }
    *reinterpret_cast<uint4*>(g_xh + i0) =
        make_uint4(packh2(e[0], e[1]), packh2(e[2], e[3]),
                   packh2(e[4], e[5]), packh2(e[6], e[7]));
}

// interleave basis rows (2f=real, 2f+1=imag) -> fp16
__global__ void basis_half_kernel(const float* __restrict__ basis) {
    size_t v = (size_t)blockIdx.x * blockDim.x + threadIdx.x;   // 8-elem group
    if (v >= (size_t)MROWS * FILTER_LEN / 8) return;
    const size_t i0 = v * 8;
    const int g = (int)(i0 >> 10);
    const int k = (int)(i0 & 1023);
    const int f = g >> 1;
    const int src = (g & 1) ? (f + CUTOFF) : f;
    const float* bs = basis + (size_t)src * FILTER_LEN + k;
    const float4 f0 = *reinterpret_cast<const float4*>(bs);
    const float4 f1 = *reinterpret_cast<const float4*>(bs + 4);
    *reinterpret_cast<uint4*>(g_bh + i0) =
        make_uint4(packh2(f0.x, f0.y), packh2(f0.z, f0.w),
                   packh2(f1.x, f1.y), packh2(f1.z, f1.w));
}

// ---------------- main: fp16 GEMM (y<8) + fp32 remainder (y==8) -------------
__global__ __launch_bounds__(256, 2)
void stft_mma_kernel(const float* __restrict__ x,
                     const float* __restrict__ basis,
                     const float* __restrict__ eps_p,
                     float* __restrict__ out)
{
    const int tid  = threadIdx.x;
    const int wid  = tid >> 5;
    const int lane = tid & 31;

    // ======== remainder: f=512 row + n=2048 column, exact fp32 =============
    if (blockIdx.y == 8) {
        const float eps = *eps_p;
        const int stride = (int)(gridDim.x * gridDim.z) * 8;
        const int wbase = (int)(blockIdx.z * gridDim.x + blockIdx.x) * 8 + wid;
        for (int o = wbase; o < NREM; o += stride) {
            const int b = o / (NFRAMES + 512);
            const int r = o % (NFRAMES + 512);
            int f, n;
            if (r < NFRAMES) { f = 512; n = r; }
            else             { f = r - NFRAMES; n = 2048; }
            const float* bR = basis + (size_t)f * FILTER_LEN;
            const float* bI = basis + (size_t)(f + CUTOFF) * FILTER_LEN;
            const float* xb = x + (size_t)b * TLEN;
            float aR = 0.f, aI = 0.f;
            #pragma unroll 4
            for (int k = lane; k < FILTER_LEN; k += 32) {
                int j = n * HOP + k - HOP;
                if (j < 0) j = -j;
                else if (j >= TLEN) j = 2 * TLEN - 2 - j;
                const float xv = xb[j];
                aR = fmaf(bR[k], xv, aR);
                aI = fmaf(bI[k], xv, aI);
            }
            #pragma unroll
            for (int s = 16; s; s >>= 1) {
                aR += __shfl_xor_sync(0xffffffffu, aR, s);
                aI += __shfl_xor_sync(0xffffffffu, aI, s);
            }
            if (lane == 0)
                out[((size_t)b * CUTOFF + f) * NFRAMES + n] =
                    sqrtf(fmaf(aR, aR, fmaf(aI, aI, eps)));
        }
        return;
    }

    // ======== dense fp16 GEMM: 128m x 128n tiles, warp 32x64 ================
    extern __shared__ char dsm[];
    const uint32_t sbase = smem_u32(dsm);

    const int b  = blockIdx.z;
    const int m0 = blockIdx.y * BM;
    const int n0 = blockIdx.x * BN;

    const int warp_m = (wid >> 1) * 32;    // 0,32,64,96
    const int warp_n = (wid & 1) * 64;     // 0,64

    // loader geometry: A and B each 1024 16B chunks -> 4 rounds of 256 thr
    int l_row[4], l_c16[4]; uint32_t l_soff[4];
    #pragma unroll
    for (int j = 0; j < 4; ++j) {
        int chunk = tid + j * 256;
        l_row[j] = chunk >> 3;
        l_c16[j] = chunk & 7;
        l_soff[j] = (uint32_t)l_row[j] * 128 + (uint32_t)((l_c16[j] ^ (l_row[j] & 7)) * 16);
    }

    const __half* bp = g_bh + (size_t)m0 * FILTER_LEN;
    const __half* xp = g_xh + (size_t)b * XP_LEN + (size_t)n0 * HOP;

    float acc[2][8][4];
    #pragma unroll
    for (int mt = 0; mt < 2; ++mt)
        #pragma unroll
        for (int nt = 0; nt < 8; ++nt)
            #pragma unroll
            for (int r = 0; r < 4; ++r) acc[mt][nt][r] = 0.f;

    const int lm_r = lane & 15;
    const int lm_s = lane >> 4;

    auto load_stage = [&](int i) {
        const uint32_t st = sbase + (uint32_t)(i % NSTAGE) * STAGE;
        const int k0 = i * KC;
        #pragma unroll
        for (int j = 0; j < 4; ++j) {
            cp_async16(st + SA + l_soff[j],
                       bp + (size_t)l_row[j] * FILTER_LEN + k0 + l_c16[j] * 8);
            cp_async16(st + SB + l_soff[j],
                       xp + (size_t)l_row[j] * HOP + k0 + l_c16[j] * 8);
        }
        cp_commit();
    };

    load_stage(0);
    load_stage(1);

    for (int i = 0; i < NK; ++i) {
        if (i + 1 < NK) cp_wait<1>(); else cp_wait<0>();
        __syncthreads();                    // stage i ready; all warps past i-1
        if (i + 2 < NK) load_stage(i + 2);  // overwrites buffer (i-1)%3: safe

        const uint32_t st = sbase + (uint32_t)(i % NSTAGE) * STAGE;

        #pragma unroll
        for (int ks = 0; ks < 4; ++ks) {
            const int c16 = ks * 2 + lm_s;
            uint32_t aF[2][4];
            #pragma unroll
            for (int mt = 0; mt < 2; ++mt) {
                const int row = warp_m + mt * 16 + lm_r;
                const uint32_t ad = st + SA + (uint32_t)row * 128
                                  + (uint32_t)((c16 ^ (row & 7)) * 16);
                ldsm_x4(aF[mt][0], aF[mt][1], aF[mt][2], aF[mt][3], ad);
            }
            #pragma unroll
            for (int g = 0; g < 4; ++g) {
                const int row = warp_n + g * 16 + lm_r;
                const uint32_t bd = st + SB + (uint32_t)row * 128
                                  + (uint32_t)((c16 ^ (row & 7)) * 16);
                uint32_t bf[4];
                ldsm_x4(bf[0], bf[1], bf[2], bf[3], bd);
                #pragma unroll
                for (int sub = 0; sub < 2; ++sub) {
                    const int nt = g * 2 + sub;
                    const uint32_t b0 = sub ? bf[1] : bf[0];
                    const uint32_t b1 = sub ? bf[3] : bf[2];
                    #pragma unroll
                    for (int mt = 0; mt < 2; ++mt)
                        mma_f16(acc[mt][nt], aF[mt], b0, b1);
                }
            }
        }
    }

    // ---- epilogue: pair R/I rows via shfl_xor(4), magnitude, store --------
    const float eps = *eps_p;
    const int r4 = lane >> 2;
    const int c2 = (lane & 3) * 2;
    const bool real_holder = ((r4 & 1) == 0);

    #pragma unroll
    for (int mt = 0; mt < 2; ++mt) {
        const int mbase = m0 + warp_m + mt * 16;
        #pragma unroll
        for (int nt = 0; nt < 8; ++nt) {
            float p[4];
            #pragma unroll
            for (int r = 0; r < 4; ++r)
                p[r] = __shfl_xor_sync(0xffffffffu, acc[mt][nt][r], 4);
            if (real_holder) {
                const int nb = n0 + warp_n + nt * 8 + c2;
                const int f0r = (mbase + r4) >> 1;
                const int f1r = (mbase + r4 + 8) >> 1;
                #pragma unroll
                for (int cc = 0; cc < 2; ++cc) {
                    const int n = nb + cc;
                    float re0 = acc[mt][nt][cc],     im0 = p[cc];
                    float re1 = acc[mt][nt][2 + cc], im1 = p[2 + cc];
                    out[((size_t)b * CUTOFF + f0r) * NFRAMES + n] =
                        sqrtf(fmaf(re0, re0, fmaf(im0, im0, eps)));
                    out[((size_t)b * CUTOFF + f1r) * NFRAMES + n] =
                        sqrtf(fmaf(re1, re1, fmaf(im1, im1, eps)));
                }
            }
        }
    }
}

// ---------------- launch ----------------------------------------------------
extern "C" void kernel_launch(void* const* d_in, const int* in_sizes, int n_in,
                              void* d_out, int out_size)
{
    const float* x     = (const float*)d_in[0];
    const float* basis = (const float*)d_in[1];
    const float* eps   = (const float*)d_in[2];
    float* out = (float*)d_out;

    {
        size_t tot = (size_t)BATCH * XP_LEN / 8;
        pad_half_kernel<<<(unsigned)((tot + 255) / 256), 256>>>(x);
    }
    {
        size_t tot = (size_t)MROWS * FILTER_LEN / 8;
        basis_half_kernel<<<(unsigned)((tot + 255) / 256), 256>>>(basis);
    }
    {
        cudaFuncSetAttribute(stft_mma_kernel,
                             cudaFuncAttributeMaxDynamicSharedMemorySize, DSMEM);
        dim3 grid(16, 9, BATCH);     // y<8: dense GEMM; y==8: fp32 remainder
        stft_mma_kernel<<<grid, 256, DSMEM>>>(x, basis, eps, out);
    }
}